// round 13
// baseline (speedup 1.0000x reference)
#include <cuda_runtime.h>
#include <cuda_bf16.h>

// TERMINAL FORM (reverts the R12 CTA-narrowing regression; identical to the
// measured-best R11 configuration, wall 4.576us, body 3.94us vs 3.46us
// no-op launch floor).
//
// Single fused kernel, 512 threads, warp-private presence+loss.
// Warp w owns batch w: the class-presence mask lives in registers (every
// lane, via __reduce_or_sync) and never touches shared memory.
//
// Presence decided from a 256-element sampled prefix (32 lanes x 2 int4).
// If the sampled mask is full, remaining labels provably cannot change the
// (monotone) OR; miss prob ~1.9e-5/batch on uniform labels. An unsaturated
// warp scans its own batch alone (chunked, warp-uniform early exit) --
// correct for arbitrary inputs. Decision depends only on input data:
// same inputs -> same work -> same output.
//
// Critical-path layout:
//  - LDG issue first (minimal prologue), straight-line fast path (no loop)
//  - BOTH fixed-point loss candidates precomputed in the load shadow, so
//    post-mask path is SEL -> REDUX.SUM only
//  - integer REDUX at both reduction levels (sm_103a has int REDUX only;
//    redux.f32 is sm_100a-only and fails ptxas here)
//  - split named barrier: warps 1..15 bar.arrive and retire; warp 0
//    bar.sync's and finishes alone (I2F -> FMUL -> STG)

#define FPSCALE 65536.0f

__global__ void fused_segenc_loss_kernel(const float* __restrict__ preds,
                                         const int*   __restrict__ targets,
                                         float* __restrict__ out,
                                         int B, int C, int n_per_batch,
                                         float out_scale) {
    __shared__ int warp_sums[32];

    const int t      = threadIdx.x;
    const int w      = t >> 5;
    const int lane   = t & 31;
    const int nwarps = blockDim.x >> 5;
    const unsigned int full_mask = (1u << C) - 1u;
    const bool vec_ok = ((n_per_batch & 3) == 0);
    const int total4  = n_per_batch >> 2;

    int ai = 0;

    if (vec_ok && B <= nwarps) {
        // ======== fast path: one batch per warp, straight-line ========
        if (w < B) {
            // ---- issue sample loads immediately (minimal prologue)
            const int4* __restrict__ t4 =
                reinterpret_cast<const int4*>(targets) + (size_t)w * total4;
            const int limit = min(64, total4);
            int4 v0 = make_int4(0, 0, 0, 0), v1 = make_int4(0, 0, 0, 0);
            const bool p0 = lane < limit;
            const bool p1 = lane + 32 < limit;
            if (p0) v0 = t4[lane];
            if (p1) v1 = t4[lane + 32];

            // ---- preds + transcendentals + BOTH fixed-point candidates,
            //      all inside the load shadow
            float x = 0.0f;
            if (lane < C) x = __ldg(&preds[w * C + lane]);
            const float l   = log1pf(expf(-fabsf(x)));  // = -logsig(|x|)
            const float lsp = fminf(x, 0.0f) - l;       // logsig(x)
            const float lsn = fminf(-x, 0.0f) - l;      // logsig(-x)
            const int ip = __float2int_rn(-lsp * FPSCALE);
            const int iq = __float2int_rn(-lsn * FPSCALE);

            // ---- presence mask from sampled prefix
            unsigned int m = 0u;
            if (p0) m |= (1u << (v0.x & 31)) | (1u << (v0.y & 31)) |
                         (1u << (v0.z & 31)) | (1u << (v0.w & 31));
            if (p1) m |= (1u << (v1.x & 31)) | (1u << (v1.y & 31)) |
                         (1u << (v1.z & 31)) | (1u << (v1.w & 31));
            unsigned int wm = __reduce_or_sync(0xffffffffu, m);

            // ---- rare fallback: scan own batch, warp-uniform early exit
            if ((wm & full_mask) != full_mask) {
                const int* __restrict__ tb =
                    targets + (size_t)w * n_per_batch;
                for (int base = 0; base < n_per_batch; base += 4096) {
                    const int end = min(base + 4096, n_per_batch);
                    unsigned int mm = 0u;
                    for (int i = base + lane; i < end; i += 32)
                        mm |= 1u << (tb[i] & 31);
                    wm |= __reduce_or_sync(0xffffffffu, mm);
                    if ((wm & full_mask) == full_mask) break;
                }
            }

            // ---- post-mask path: pure select
            if (lane < C) ai = ((wm >> lane) & 1u) ? ip : iq;
        }
    } else {
        // ======== generic path: scalar loop, any shape ========
        float acc = 0.0f;
        for (int bb = w; bb < B; bb += nwarps) {
            float x = 0.0f;
            if (lane < C) x = __ldg(&preds[bb * C + lane]);
            const float l   = log1pf(expf(-fabsf(x)));
            const float lsp = fminf(x, 0.0f) - l;
            const float lsn = fminf(-x, 0.0f) - l;

            unsigned int wm = 0u;
            const int* __restrict__ tb = targets + (size_t)bb * n_per_batch;
            for (int base = 0; base < n_per_batch; base += 4096) {
                const int end = min(base + 4096, n_per_batch);
                unsigned int mm = 0u;
                for (int i = base + lane; i < end; i += 32)
                    mm |= 1u << (tb[i] & 31);
                wm |= __reduce_or_sync(0xffffffffu, mm);
                if ((wm & full_mask) == full_mask) break;
            }
            if (lane < C) acc += -(((wm >> lane) & 1u) ? lsp : lsn);
        }
        ai = __float2int_rn(acc * FPSCALE);
    }

    // ---- warp sum: single REDUX.SUM, store partial
    const int wsum = __reduce_add_sync(0xffffffffu, ai);
    if (lane == 0) warp_sums[w] = wsum;

    // ---- split barrier: non-zero warps arrive and retire; warp 0 syncs
    //      and reduces the partials with one more REDUX.
    const unsigned int nthreads = blockDim.x;
    if (w != 0) {
        asm volatile("bar.arrive 1, %0;" :: "r"(nthreads) : "memory");
    } else {
        asm volatile("bar.sync 1, %0;" :: "r"(nthreads) : "memory");
        const int p = (lane < nwarps) ? warp_sums[lane] : 0;
        const int s = __reduce_add_sync(0xffffffffu, p);
        if (lane == 0) out[0] = (float)s * out_scale;
    }
}

extern "C" void kernel_launch(void* const* d_in, const int* in_sizes, int n_in,
                              void* d_out, int out_size) {
    const float* preds   = (const float*)d_in[0];
    const int*   targets = (const int*)d_in[1];

    const int C = 19;                       // NUM_CLASSES (fixed by problem)
    const int B = in_sizes[0] / C;          // 16
    const int n_per_batch = in_sizes[1] / B;
    const float out_scale = 1.0f / ((float)(B * C) * FPSCALE);

    fused_segenc_loss_kernel<<<1, 512>>>(preds, targets, (float*)d_out,
                                         B, C, n_per_batch, out_scale);
}

// round 14
// speedup vs baseline: 1.5211x; 1.5211x over previous
#include <cuda_runtime.h>
#include <cuda_bf16.h>

// TERMINAL FORM — identical to the measured-best R11 configuration
// (wall 4.576us / body 3.94us vs 3.46us no-op launch floor; R13 re-run of
// the same source measured 6.91us, establishing ~2.3us replay-clock wall
// variance — body under ncu's fixed clock is the reliable metric).
//
// Single fused kernel, 512 threads, warp-private presence+loss.
// Warp w owns batch w: the class-presence mask lives in registers (every
// lane, via __reduce_or_sync) and never touches shared memory.
//
// Presence decided from a 256-element sampled prefix (32 lanes x 2 int4).
// If the sampled mask is full, remaining labels provably cannot change the
// (monotone) OR; miss prob ~1.9e-5/batch on uniform labels. An unsaturated
// warp scans its own batch alone (chunked, warp-uniform early exit) --
// correct for arbitrary inputs. Decision depends only on input data:
// same inputs -> same work -> same output.
//
// Critical-path layout:
//  - LDG issue first (minimal prologue), straight-line fast path (no loop)
//  - BOTH fixed-point loss candidates precomputed in the load shadow, so
//    post-mask path is SEL -> REDUX.SUM only
//  - integer REDUX at both reduction levels (sm_103a has int REDUX only;
//    redux.f32 is sm_100a-only and fails ptxas here)
//  - split named barrier: warps 1..15 bar.arrive and retire; warp 0
//    bar.sync's and finishes alone (I2F -> FMUL -> STG)
//
// Measured dead ends (do not revisit): float shared atomicAdd epilogue
// (CAS-spin serialization, +6.4us), 256-thread/2-batch-per-warp shape
// (serialized per-warp chain, +2us), shuffle-tree epilogues (slower than
// REDUX by ~200 cyc).

#define FPSCALE 65536.0f

__global__ void __launch_bounds__(512, 1)
fused_segenc_loss_kernel(const float* __restrict__ preds,
                         const int*   __restrict__ targets,
                         float* __restrict__ out,
                         int B, int C, int n_per_batch,
                         float out_scale) {
    __shared__ int warp_sums[32];

    const int t      = threadIdx.x;
    const int w      = t >> 5;
    const int lane   = t & 31;
    const int nwarps = blockDim.x >> 5;
    const unsigned int full_mask = (1u << C) - 1u;
    const bool vec_ok = ((n_per_batch & 3) == 0);
    const int total4  = n_per_batch >> 2;

    int ai = 0;

    if (vec_ok && B <= nwarps) {
        // ======== fast path: one batch per warp, straight-line ========
        if (w < B) {
            // ---- issue sample loads immediately (minimal prologue)
            const int4* __restrict__ t4 =
                reinterpret_cast<const int4*>(targets) + (size_t)w * total4;
            const int limit = min(64, total4);
            int4 v0 = make_int4(0, 0, 0, 0), v1 = make_int4(0, 0, 0, 0);
            const bool p0 = lane < limit;
            const bool p1 = lane + 32 < limit;
            if (p0) v0 = t4[lane];
            if (p1) v1 = t4[lane + 32];

            // ---- preds + transcendentals + BOTH fixed-point candidates,
            //      all inside the load shadow
            float x = 0.0f;
            if (lane < C) x = __ldg(&preds[w * C + lane]);
            const float l   = log1pf(expf(-fabsf(x)));  // = -logsig(|x|)
            const float lsp = fminf(x, 0.0f) - l;       // logsig(x)
            const float lsn = fminf(-x, 0.0f) - l;      // logsig(-x)
            const int ip = __float2int_rn(-lsp * FPSCALE);
            const int iq = __float2int_rn(-lsn * FPSCALE);

            // ---- presence mask from sampled prefix
            unsigned int m = 0u;
            if (p0) m |= (1u << (v0.x & 31)) | (1u << (v0.y & 31)) |
                         (1u << (v0.z & 31)) | (1u << (v0.w & 31));
            if (p1) m |= (1u << (v1.x & 31)) | (1u << (v1.y & 31)) |
                         (1u << (v1.z & 31)) | (1u << (v1.w & 31));
            unsigned int wm = __reduce_or_sync(0xffffffffu, m);

            // ---- rare fallback: scan own batch, warp-uniform early exit
            if ((wm & full_mask) != full_mask) {
                const int* __restrict__ tb =
                    targets + (size_t)w * n_per_batch;
                for (int base = 0; base < n_per_batch; base += 4096) {
                    const int end = min(base + 4096, n_per_batch);
                    unsigned int mm = 0u;
                    for (int i = base + lane; i < end; i += 32)
                        mm |= 1u << (tb[i] & 31);
                    wm |= __reduce_or_sync(0xffffffffu, mm);
                    if ((wm & full_mask) == full_mask) break;
                }
            }

            // ---- post-mask path: pure select
            if (lane < C) ai = ((wm >> lane) & 1u) ? ip : iq;
        }
    } else {
        // ======== generic path: scalar loop, any shape ========
        float acc = 0.0f;
        for (int bb = w; bb < B; bb += nwarps) {
            float x = 0.0f;
            if (lane < C) x = __ldg(&preds[bb * C + lane]);
            const float l   = log1pf(expf(-fabsf(x)));
            const float lsp = fminf(x, 0.0f) - l;
            const float lsn = fminf(-x, 0.0f) - l;

            unsigned int wm = 0u;
            const int* __restrict__ tb = targets + (size_t)bb * n_per_batch;
            for (int base = 0; base < n_per_batch; base += 4096) {
                const int end = min(base + 4096, n_per_batch);
                unsigned int mm = 0u;
                for (int i = base + lane; i < end; i += 32)
                    mm |= 1u << (tb[i] & 31);
                wm |= __reduce_or_sync(0xffffffffu, mm);
                if ((wm & full_mask) == full_mask) break;
            }
            if (lane < C) acc += -(((wm >> lane) & 1u) ? lsp : lsn);
        }
        ai = __float2int_rn(acc * FPSCALE);
    }

    // ---- warp sum: single REDUX.SUM, store partial
    const int wsum = __reduce_add_sync(0xffffffffu, ai);
    if (lane == 0) warp_sums[w] = wsum;

    // ---- split barrier: non-zero warps arrive and retire; warp 0 syncs
    //      and reduces the partials with one more REDUX.
    const unsigned int nthreads = blockDim.x;
    if (w != 0) {
        asm volatile("bar.arrive 1, %0;" :: "r"(nthreads) : "memory");
    } else {
        asm volatile("bar.sync 1, %0;" :: "r"(nthreads) : "memory");
        const int p = (lane < nwarps) ? warp_sums[lane] : 0;
        const int s = __reduce_add_sync(0xffffffffu, p);
        if (lane == 0) out[0] = (float)s * out_scale;
    }
}

extern "C" void kernel_launch(void* const* d_in, const int* in_sizes, int n_in,
                              void* d_out, int out_size) {
    const float* preds   = (const float*)d_in[0];
    const int*   targets = (const int*)d_in[1];

    const int C = 19;                       // NUM_CLASSES (fixed by problem)
    const int B = in_sizes[0] / C;          // 16
    const int n_per_batch = in_sizes[1] / B;
    const float out_scale = 1.0f / ((float)(B * C) * FPSCALE);

    fused_segenc_loss_kernel<<<1, 512>>>(preds, targets, (float*)d_out,
                                         B, C, n_per_batch, out_scale);
}